// round 4
// baseline (speedup 1.0000x reference)
#include <cuda_runtime.h>
#include <math.h>
#include <float.h>

#define B_ROWS 256
#define N_COLS 65536
#define THREADS 512
#define NWARP (THREADS / 32)

// Scratch for per-row losses (no allocation allowed in kernel_launch)
__device__ float g_row_loss[B_ROWS];

__device__ __forceinline__ float warpMaxf(float v) {
#pragma unroll
    for (int o = 16; o > 0; o >>= 1)
        v = fmaxf(v, __shfl_xor_sync(0xffffffffu, v, o));
    return v;
}
__device__ __forceinline__ float warpSumf(float v) {
#pragma unroll
    for (int o = 16; o > 0; o >>= 1)
        v += __shfl_xor_sync(0xffffffffu, v, o);
    return v;
}
__device__ __forceinline__ int warpSumi(int v) {
#pragma unroll
    for (int o = 16; o > 0; o >>= 1)
        v += __shfl_xor_sync(0xffffffffu, v, o);
    return v;
}

// Process one (sim, label) element. All logits are in [0, 40.96] so
// summing exp() directly (no max-shift) is overflow-safe in fp32.
__device__ __forceinline__ void process_elem(
    float s_, float l_,
    float& sum_p, float& sum_n, int& npos, int& nneg,
    float (&top)[10], float& topmin)
{
    if (l_ > 0.5f) {
        // logit_p = 64 * relu(0.8 - s)^2
        float d = fmaxf(0.8f - s_, 0.0f);
        sum_p += __expf(64.0f * d * d);
        npos++;
    } else if (l_ < 0.25f) {
        // logit_n = 64 * relu(s - 0.2)^2   (exactly matches alpha*(s-0.2)*64)
        float e = fmaxf(s_ - 0.2f, 0.0f);
        sum_n += __expf(64.0f * e * e);
        nneg++;
        if (s_ > topmin) {
            // replace the current minimum of the 10-entry register list
            int am = 0; float mv = top[0];
#pragma unroll
            for (int k = 1; k < 10; k++)
                if (top[k] < mv) { mv = top[k]; am = k; }
#pragma unroll
            for (int k = 0; k < 10; k++)
                if (k == am) top[k] = s_;
            topmin = top[0];
#pragma unroll
            for (int k = 1; k < 10; k++) topmin = fminf(topmin, top[k]);
        }
    }
}

__global__ __launch_bounds__(THREADS, 2)
void ranking_row_kernel(const float* __restrict__ sim,
                        const float* __restrict__ lab)
{
    const int row  = blockIdx.x;
    const int tid  = threadIdx.x;
    const int lane = tid & 31;
    const int wid  = tid >> 5;

    const float4* s4 = reinterpret_cast<const float4*>(sim + (size_t)row * N_COLS);
    const float4* l4 = reinterpret_cast<const float4*>(lab + (size_t)row * N_COLS);

    float sum_p = 0.0f, sum_n = 0.0f;
    int   npos = 0, nneg = 0;
    float top[10];
#pragma unroll
    for (int k = 0; k < 10; k++) top[k] = -FLT_MAX;
    float topmin = -FLT_MAX;

    const int NV = N_COLS / 4;   // 16384 float4s
#pragma unroll 2
    for (int i = tid; i < NV; i += THREADS) {
        float4 s = s4[i];
        float4 l = l4[i];
        process_elem(s.x, l.x, sum_p, sum_n, npos, nneg, top, topmin);
        process_elem(s.y, l.y, sum_p, sum_n, npos, nneg, top, topmin);
        process_elem(s.z, l.z, sum_p, sum_n, npos, nneg, top, topmin);
        process_elem(s.w, l.w, sum_p, sum_n, npos, nneg, top, topmin);
    }

    // ---- block reductions of scalar sums ----
    __shared__ float sh_sum_p[NWARP];
    __shared__ float sh_sum_n[NWARP];
    __shared__ int   sh_npos[NWARP];
    __shared__ int   sh_nneg[NWARP];
    __shared__ float cand[NWARP * 10];

    float wp = warpSumf(sum_p);
    float wn = warpSumf(sum_n);
    int   ip = warpSumi(npos);
    int   in_ = warpSumi(nneg);
    if (lane == 0) {
        sh_sum_p[wid] = wp;
        sh_sum_n[wid] = wn;
        sh_npos[wid]  = ip;
        sh_nneg[wid]  = in_;
    }

    // ---- per-warp top-10 extraction (exact, tie-break by lowest lane) ----
    for (int r = 0; r < 10; r++) {
        float m = top[0]; int am = 0;
#pragma unroll
        for (int k = 1; k < 10; k++)
            if (top[k] > m) { m = top[k]; am = k; }
        float wmax = warpMaxf(m);
        unsigned msk = __ballot_sync(0xffffffffu, m == wmax);
        int src = __ffs(msk) - 1;
        if (lane == src) {
#pragma unroll
            for (int k = 0; k < 10; k++)
                if (k == am) top[k] = -FLT_MAX;
        }
        if (lane == 0) cand[wid * 10 + r] = wmax;
    }
    __syncthreads();

    // ---- warp 0: merge 160 candidates -> row top-10, finish the row ----
    if (wid == 0) {
        float loc[5];
#pragma unroll
        for (int k = 0; k < 5; k++)
            loc[k] = cand[lane + k * 32];   // 160 = 32*5

        float sum_top = 0.0f;
        for (int r = 0; r < 10; r++) {
            float m = loc[0]; int am = 0;
#pragma unroll
            for (int k = 1; k < 5; k++)
                if (loc[k] > m) { m = loc[k]; am = k; }
            float wmax = warpMaxf(m);
            unsigned msk = __ballot_sync(0xffffffffu, m == wmax);
            int src = __ffs(msk) - 1;
            if (lane == src) {
#pragma unroll
                for (int k = 0; k < 5; k++)
                    if (k == am) loc[k] = -FLT_MAX;
            }
            float e = fmaxf(wmax - 0.2f, 0.0f);
            sum_top += __expf(64.0f * e * e);   // replicated on all lanes; lane0 uses
        }

        float sp  = (lane < NWARP) ? sh_sum_p[lane] : 0.0f;
        float sn  = (lane < NWARP) ? sh_sum_n[lane] : 0.0f;
        int   np  = (lane < NWARP) ? sh_npos[lane]  : 0;
        int   nn  = (lane < NWARP) ? sh_nneg[lane]  : 0;
        sp = warpSumf(sp);
        sn = warpSumf(sn);
        np = warpSumi(np);
        nn = warpSumi(nn);

        if (lane == 0) {
            float lse_p = (np > 0) ? logf(sp) : 0.0f;
            float lse_n;
            if (nn > 20)      lse_n = logf(sum_top);
            else if (nn > 0)  lse_n = logf(sn);
            else              lse_n = -FLT_MAX;   // acts as -inf -> softplus 0

            float x = lse_n + lse_p;
            float sploss;
            if (x > 0.0f) sploss = x + log1pf(expf(-x));
            else          sploss = log1pf(expf(x));
            g_row_loss[row] = sploss;
        }
    }
}

__global__ void ranking_final_kernel(float* __restrict__ out)
{
    __shared__ float sh[8];
    int tid = threadIdx.x;          // 256 threads
    float v = g_row_loss[tid];
    v = warpSumf(v);
    if ((tid & 31) == 0) sh[tid >> 5] = v;
    __syncthreads();
    if (tid < 32) {
        float w = (tid < 8) ? sh[tid] : 0.0f;
        w = warpSumf(w);
        if (tid == 0) out[0] = w * (1.0f / (float)B_ROWS);
    }
}

extern "C" void kernel_launch(void* const* d_in, const int* in_sizes, int n_in,
                              void* d_out, int out_size)
{
    const float* sim = (const float*)d_in[0];
    const float* lab = (const float*)d_in[1];
    float* out = (float*)d_out;

    ranking_row_kernel<<<B_ROWS, THREADS>>>(sim, lab);
    ranking_final_kernel<<<1, 256>>>(out);
}

// round 7
// speedup vs baseline: 1.3017x; 1.3017x over previous
#include <cuda_runtime.h>
#include <math.h>
#include <float.h>

#define B_ROWS 256
#define N_COLS 65536
#define THREADS 512
#define NWARP (THREADS / 32)

// Scratch (no allocation allowed in kernel_launch)
__device__ float g_row_loss[B_ROWS];
__device__ int   g_done;          // zero-init; reset by elected block each replay

__device__ __forceinline__ float warpMaxf(float v) {
#pragma unroll
    for (int o = 16; o > 0; o >>= 1)
        v = fmaxf(v, __shfl_xor_sync(0xffffffffu, v, o));
    return v;
}
__device__ __forceinline__ float warpSumf(float v) {
#pragma unroll
    for (int o = 16; o > 0; o >>= 1)
        v += __shfl_xor_sync(0xffffffffu, v, o);
    return v;
}
__device__ __forceinline__ int warpSumi(int v) {
#pragma unroll
    for (int o = 16; o > 0; o >>= 1)
        v += __shfl_xor_sync(0xffffffffu, v, o);
    return v;
}

// exp2 argument for positives: 64*log2(e)*(0.8-sc)^2 expanded as quadratic.
// 64*log2e = 92.33248261689366 ; *1.6 = 147.73197218702986 ; *0.64 = 59.092788874811464
#define C_A  92.33248261689366f
#define C_B -147.73197218702986f
#define C_C  59.09278887481146f

__device__ __forceinline__ void process_elem(
    float s_, float l_,
    float& sum_p, float& s_min, float s_th,
    int& nneg, float (&top)[10])
{
    // ---- positives: predicated exp with adaptive cutoff ----
    bool pos  = (l_ > 0.5f);
    bool keep = pos && (s_ < s_th);
    float sc = fminf(s_, 0.8f);            // relu fold: d = 0.8 - sc >= 0
    float u  = fmaf(sc, C_A, C_B);
    float t  = fmaf(u, sc, C_C);           // = 92.332*(0.8-sc)^2
    if (keep) {
        sum_p += exp2f(t);                 // MUFU only when kept
        s_min  = fminf(s_min, s_);
    }

    // ---- negatives: count + exact top-10 (no exp) ----
    bool neg = (l_ < 0.25f);
    nneg += neg;
    bool ins = neg && (s_ > top[0]);       // top[] sorted ascending, top[0]=min
    if (__any_sync(0xffffffffu, ins)) {
        if (ins) {
#pragma unroll
            for (int k = 0; k < 9; k++) {
                float hi = fmaxf(s_, top[k]);
                top[k] = fminf(hi, top[k + 1]);
            }
            top[9] = fmaxf(s_, top[9]);
        }
    }
}

__global__ __launch_bounds__(THREADS, 2)
void ranking_fused_kernel(const float* __restrict__ sim,
                          const float* __restrict__ lab,
                          float* __restrict__ out)
{
    const int row  = blockIdx.x;
    const int tid  = threadIdx.x;
    const int lane = tid & 31;
    const int wid  = tid >> 5;

    const float4* s4 = reinterpret_cast<const float4*>(sim + (size_t)row * N_COLS);
    const float4* l4 = reinterpret_cast<const float4*>(lab + (size_t)row * N_COLS);

    float sum_p = 0.0f;
    float s_min = FLT_MAX;                 // min sim among kept positives
    float s_th  = FLT_MAX;                 // keep-threshold in s-space
    int   nneg  = 0;
    float top[10];
#pragma unroll
    for (int k = 0; k < 10; k++) top[k] = -FLT_MAX;

    // 32 iterations of float4 per thread = 8 groups x 4
#pragma unroll 1
    for (int g = 0; g < 8; g++) {
#pragma unroll
        for (int j = 0; j < 4; j++) {
            int i = tid + (g * 4 + j) * THREADS;
            float4 s = s4[i];
            float4 l = l4[i];
            process_elem(s.x, l.x, sum_p, s_min, s_th, nneg, top);
            process_elem(s.y, l.y, sum_p, s_min, s_th, nneg, top);
            process_elem(s.z, l.z, sum_p, s_min, s_th, nneg, top);
            process_elem(s.w, l.w, sum_p, s_min, s_th, nneg, top);
        }
        // refresh cutoff: keep logit >= max_logit - 16
        // max_logit = 64*dmin^2 ; threshold s: 0.8 - sqrt(dmin^2 - 0.25)
        float dmin = 0.8f - s_min;
        s_th = (dmin <= 0.500001f) ? FLT_MAX
                                   : (0.8f - sqrtf(fmaf(dmin, dmin, -0.25f)));
    }

    // ---- block reductions ----
    __shared__ float sh_sum_p[NWARP];
    __shared__ int   sh_nneg[NWARP];
    __shared__ float cand[NWARP * 10];
    __shared__ int   sh_elect;

    float wp = warpSumf(sum_p);
    int   wn = warpSumi(nneg);
    if (lane == 0) { sh_sum_p[wid] = wp; sh_nneg[wid] = wn; }

    // per-warp top-10 extraction (exact, tie-break lowest lane)
    for (int r = 0; r < 10; r++) {
        float m = top[0]; int am = 0;
#pragma unroll
        for (int k = 1; k < 10; k++)
            if (top[k] > m) { m = top[k]; am = k; }
        float wmax = warpMaxf(m);
        unsigned msk = __ballot_sync(0xffffffffu, m == wmax);
        int src = __ffs(msk) - 1;
        if (lane == src) {
#pragma unroll
            for (int k = 0; k < 10; k++)
                if (k == am) top[k] = -FLT_MAX;
        }
        if (lane == 0) cand[wid * 10 + r] = wmax;
    }
    __syncthreads();

    // ---- warp 0: merge 160 candidates -> row top-10, finish row ----
    if (wid == 0) {
        float loc[5];
#pragma unroll
        for (int k = 0; k < 5; k++)
            loc[k] = cand[lane + k * 32];

        float sum_top = 0.0f;
        for (int r = 0; r < 10; r++) {
            float m = loc[0]; int am = 0;
#pragma unroll
            for (int k = 1; k < 5; k++)
                if (loc[k] > m) { m = loc[k]; am = k; }
            float wmax = warpMaxf(m);
            unsigned msk = __ballot_sync(0xffffffffu, m == wmax);
            int src = __ffs(msk) - 1;
            if (lane == src) {
#pragma unroll
                for (int k = 0; k < 5; k++)
                    if (k == am) loc[k] = -FLT_MAX;
            }
            float e = fmaxf(wmax - 0.2f, 0.0f);
            sum_top += __expf(64.0f * e * e);
        }

        float sp = (lane < NWARP) ? sh_sum_p[lane] : 0.0f;
        int   nn = (lane < NWARP) ? sh_nneg[lane]  : 0;
        sp = warpSumf(sp);
        nn = warpSumi(nn);

        if (lane == 0) {
            float lse_p = (sp > 0.0f) ? logf(sp) : 0.0f;
            float lse_n;
            if (nn > 20) {
                lse_n = logf(sum_top);
            } else if (nn > 0) {
                // exact fallback (practically never taken): serial rescan
                const float* ss = sim + (size_t)row * N_COLS;
                const float* ll = lab + (size_t)row * N_COLS;
                float sn = 0.0f;
                for (int i = 0; i < N_COLS; i++) {
                    if (ll[i] < 0.25f) {
                        float e = fmaxf(ss[i] - 0.2f, 0.0f);
                        sn += __expf(64.0f * e * e);
                    }
                }
                lse_n = logf(sn);
            } else {
                lse_n = -FLT_MAX;          // acts as -inf -> softplus 0
            }

            float x = lse_n + lse_p;
            float sploss;
            if (x > 0.0f) sploss = x + log1pf(expf(-x));
            else          sploss = log1pf(expf(x));
            g_row_loss[row] = sploss;
            __threadfence();
        }
    }
    __syncthreads();

    // ---- last block finishes: deterministic tree sum of 256 row losses ----
    if (tid == 0)
        sh_elect = (atomicAdd(&g_done, 1) == (B_ROWS - 1)) ? 1 : 0;
    __syncthreads();
    if (sh_elect) {
        __threadfence();
        __shared__ float shf[8];
        float v = (tid < B_ROWS) ? g_row_loss[tid] : 0.0f;
        v = warpSumf(v);
        if (lane == 0 && wid < 8) shf[wid] = v;
        __syncthreads();
        if (tid < 32) {
            float w = (tid < 8) ? shf[tid] : 0.0f;
            w = warpSumf(w);
            if (tid == 0) {
                out[0] = w * (1.0f / (float)B_ROWS);
                g_done = 0;                // reset for next graph replay
            }
        }
    }
}

extern "C" void kernel_launch(void* const* d_in, const int* in_sizes, int n_in,
                              void* d_out, int out_size)
{
    const float* sim = (const float*)d_in[0];
    const float* lab = (const float*)d_in[1];
    float* out = (float*)d_out;

    ranking_fused_kernel<<<B_ROWS, THREADS>>>(sim, lab, out);
}

// round 8
// speedup vs baseline: 2.8098x; 2.1585x over previous
#include <cuda_runtime.h>
#include <math.h>
#include <float.h>

#define B_ROWS 256
#define N_COLS 65536
#define SPLIT  4
#define CHUNK  (N_COLS / SPLIT)        // 16384 elements per CTA
#define T1     256                     // threads in pass-1 CTA
#define NCHUNK (B_ROWS * SPLIT)        // 1024 CTAs
#define CAP    256                     // candidate buffer per row
#define THRESH 0.998f                  // negative top-10 prefilter

// Scratch (static device globals; no runtime allocation)
__device__ float g_sum_p[NCHUNK];
__device__ int   g_nneg[NCHUNK];
__device__ int   g_cnt[B_ROWS];        // zero-init; finisher resets each replay
__device__ float g_cand[B_ROWS * CAP];

__device__ __forceinline__ float warpSumf(float v) {
#pragma unroll
    for (int o = 16; o > 0; o >>= 1)
        v += __shfl_xor_sync(0xffffffffu, v, o);
    return v;
}
__device__ __forceinline__ int warpSumi(int v) {
#pragma unroll
    for (int o = 16; o > 0; o >>= 1)
        v += __shfl_xor_sync(0xffffffffu, v, o);
    return v;
}

// exp2 argument for positives: 92.33248*(0.8-sc)^2 expanded as quadratic in sc
// (92.33248 = 64*log2(e), so exp2(t) == exp(64*(0.8-sc)^2))
#define C_A  92.33248261689366f
#define C_B -147.73197218702986f
#define C_C  59.09278887481146f

__device__ __forceinline__ void process_elem(
    float s_, float l_,
    float& sum_p, float& s_min, float s_th,
    int& nneg, int* cnt_ptr, float* cand_ptr)
{
    // ---- positives: predicated exp with adaptive cutoff ----
    bool pos  = (l_ > 0.5f);
    bool keep = pos && (s_ < s_th);
    float sc = fminf(s_, 0.8f);
    float u  = fmaf(sc, C_A, C_B);
    float t  = fmaf(u, sc, C_C);            // = 92.332*(0.8-sc)^2
    if (keep) {
        sum_p += exp2f(t);                  // MUFU only when kept (~13% of elems)
        s_min  = fminf(s_min, s_);
    }

    // ---- negatives: count + rare candidate push (no per-elem top-10) ----
    bool neg = (l_ < 0.25f);
    nneg += neg;
    if (neg && (s_ > THRESH)) {             // ~1 hit per warp per kernel
        int idx = atomicAdd(cnt_ptr, 1);
        if (idx < CAP) cand_ptr[idx] = s_;
    }
}

__global__ __launch_bounds__(T1)
void ranking_pass1(const float* __restrict__ sim,
                   const float* __restrict__ lab)
{
    const int chunk = blockIdx.x;
    const int row   = chunk >> 2;           // SPLIT = 4
    const int part  = chunk & 3;
    const int tid   = threadIdx.x;
    const int lane  = tid & 31;
    const int wid   = tid >> 5;

    const size_t base = (size_t)row * N_COLS + (size_t)part * CHUNK;
    const float4* s4 = reinterpret_cast<const float4*>(sim + base);
    const float4* l4 = reinterpret_cast<const float4*>(lab + base);

    int*   cnt_ptr  = &g_cnt[row];
    float* cand_ptr = &g_cand[row * CAP];

    float sum_p = 0.0f;
    float s_min = FLT_MAX;
    float s_th  = FLT_MAX;
    int   nneg  = 0;

    // CHUNK/4 = 4096 float4s, 256 threads -> 16 float4 per thread.
    // 4 groups of 4 float4, threshold refresh between groups.
#pragma unroll 1
    for (int g = 0; g < 4; g++) {
#pragma unroll
        for (int j = 0; j < 4; j++) {
            int i = tid + (g * 4 + j) * T1;
            float4 s = s4[i];
            float4 l = l4[i];
            process_elem(s.x, l.x, sum_p, s_min, s_th, nneg, cnt_ptr, cand_ptr);
            process_elem(s.y, l.y, sum_p, s_min, s_th, nneg, cnt_ptr, cand_ptr);
            process_elem(s.z, l.z, sum_p, s_min, s_th, nneg, cnt_ptr, cand_ptr);
            process_elem(s.w, l.w, sum_p, s_min, s_th, nneg, cnt_ptr, cand_ptr);
        }
        // keep logit >= local_max_logit - 16:
        // max = 64*dmin^2 ; keep s <= 0.8 - sqrt(dmin^2 - 0.25)
        float dmin = 0.8f - s_min;
        s_th = (dmin <= 0.500001f) ? FLT_MAX
                                   : (0.8f - sqrtf(fmaf(dmin, dmin, -0.25f)));
    }

    // block reduction of sum_p / nneg
    __shared__ float sh_p[T1 / 32];
    __shared__ int   sh_n[T1 / 32];
    float wp = warpSumf(sum_p);
    int   wn = warpSumi(nneg);
    if (lane == 0) { sh_p[wid] = wp; sh_n[wid] = wn; }
    __syncthreads();
    if (tid < 32) {
        float p = (tid < T1 / 32) ? sh_p[tid] : 0.0f;
        int   n = (tid < T1 / 32) ? sh_n[tid] : 0;
        p = warpSumf(p);
        n = warpSumi(n);
        if (tid == 0) { g_sum_p[chunk] = p; g_nneg[chunk] = n; }
    }
}

__global__ __launch_bounds__(B_ROWS)
void ranking_finish(const float* __restrict__ sim,
                    const float* __restrict__ lab,
                    float* __restrict__ out)
{
    const int tid  = threadIdx.x;       // one thread per row
    const int row  = tid;
    const int lane = tid & 31;
    const int wid  = tid >> 5;

    float sp = 0.0f; int nn = 0;
#pragma unroll
    for (int c = 0; c < SPLIT; c++) {
        sp += g_sum_p[row * SPLIT + c];
        nn += g_nneg[row * SPLIT + c];
    }
    int cnt = g_cnt[row];
    g_cnt[row] = 0;                     // reset for next graph replay

    float lse_n;
    if (nn > 20 && cnt >= 10 && cnt <= CAP) {
        // fast path: exact top-10 from candidate multiset (order-invariant)
        float top[10];
#pragma unroll
        for (int k = 0; k < 10; k++) top[k] = -FLT_MAX;
        for (int i = 0; i < cnt; i++) {
            float v = g_cand[row * CAP + i];
            if (v > top[0]) {           // top[] sorted ascending
#pragma unroll
                for (int k = 0; k < 9; k++) {
                    float hi = fmaxf(v, top[k]);
                    top[k] = fminf(hi, top[k + 1]);
                }
                top[9] = fmaxf(v, top[9]);
            }
        }
        float sum_top = 0.0f;
#pragma unroll
        for (int k = 0; k < 10; k++) {
            float e = fmaxf(top[k] - 0.2f, 0.0f);
            sum_top += __expf(64.0f * e * e);
        }
        lse_n = logf(sum_top);
    } else if (nn > 0) {
        // slow exact fallback (never taken on this data): serial row scan
        const float* ss = sim + (size_t)row * N_COLS;
        const float* ll = lab + (size_t)row * N_COLS;
        float sum_n = 0.0f;
        float top[10];
#pragma unroll
        for (int k = 0; k < 10; k++) top[k] = -FLT_MAX;
        for (int i = 0; i < N_COLS; i++) {
            if (ll[i] < 0.25f) {
                float s_ = ss[i];
                float e = fmaxf(s_ - 0.2f, 0.0f);
                sum_n += __expf(64.0f * e * e);
                if (s_ > top[0]) {
#pragma unroll
                    for (int k = 0; k < 9; k++) {
                        float hi = fmaxf(s_, top[k]);
                        top[k] = fminf(hi, top[k + 1]);
                    }
                    top[9] = fmaxf(s_, top[9]);
                }
            }
        }
        if (nn > 20) {
            float sum_top = 0.0f;
#pragma unroll
            for (int k = 0; k < 10; k++) {
                float e = fmaxf(top[k] - 0.2f, 0.0f);
                sum_top += __expf(64.0f * e * e);
            }
            lse_n = logf(sum_top);
        } else {
            lse_n = logf(sum_n);
        }
    } else {
        lse_n = -FLT_MAX;               // no negatives: acts as -inf
    }

    float lse_p = (sp > 0.0f) ? logf(sp) : 0.0f;

    float x = lse_n + lse_p;
    float sploss;
    if (x > 0.0f) sploss = x + log1pf(expf(-x));
    else          sploss = log1pf(expf(x));

    // deterministic block-tree mean over 256 rows
    __shared__ float shf[B_ROWS / 32];
    float v = warpSumf(sploss);
    if (lane == 0) shf[wid] = v;
    __syncthreads();
    if (tid < 32) {
        float w = (tid < B_ROWS / 32) ? shf[tid] : 0.0f;
        w = warpSumf(w);
        if (tid == 0) out[0] = w * (1.0f / (float)B_ROWS);
    }
}

extern "C" void kernel_launch(void* const* d_in, const int* in_sizes, int n_in,
                              void* d_out, int out_size)
{
    const float* sim = (const float*)d_in[0];
    const float* lab = (const float*)d_in[1];
    float* out = (float*)d_out;

    ranking_pass1<<<NCHUNK, T1>>>(sim, lab);
    ranking_finish<<<1, B_ROWS>>>(sim, lab, out);
}